// round 11
// baseline (speedup 1.0000x reference)
#include <cuda_runtime.h>
#include <cuda_bf16.h>
#include <cstdint>

#define B_  64
#define T_  512
#define H_  512
#define NCTA 128

// padded h rows: 520 bf16 = 1040B -> conflict-free ldmatrix; one 16-batch
// stripe (16x520x2 = 16640B) is a contiguous bulk-copy block.
#define HB 520
#define STRIPE (16 * HB * 2)                // 16640 bytes
#define HSLICE (B_ * HB * 2)                // 66560 bytes
#define SM_HH 0
#define SM_HL HSLICE                        // 66560
#define SM_WH (2 * HSLICE)                  // 133120
#define SM_WL (SM_WH + 32 * HB * 2)         // 166400
#define SM_MB (SM_WL + 32 * HB * 2)         // 199680 (4 mbarriers)
#define PERSIST_SMEM (SM_MB + 64)           // 199744

typedef unsigned long long u64;

// ---------------- scratch (device globals; no runtime allocation) ----------
__device__ float g_pre[2][T_][B_][2048];            // x@Wih^T + bias  (512 MB)
__device__ __align__(16) __nv_bfloat16 g_hh[2][2][B_][HB];   // h hi (padded rows)
__device__ __align__(16) __nv_bfloat16 g_hl[2][2][B_][HB];   // h lo
__device__ unsigned g_cnt[2 * 32];                  // per-dir arrival counter
__device__ unsigned g_flag[2 * 32];                 // per-dir epoch flag (separate line)

// ---------------- helpers -----------------------------------------------------
__device__ __forceinline__ void ffma2(u64& d, u64 a, u64 b) {
    asm("fma.rn.f32x2 %0, %1, %2, %0;" : "+l"(d) : "l"(a), "l"(b));
}
__device__ __forceinline__ float hsum2(u64 v) {
    float lo, hi;
    asm("mov.b64 {%0,%1}, %2;" : "=f"(lo), "=f"(hi) : "l"(v));
    return lo + hi;
}
__device__ __forceinline__ unsigned ld_acq(const unsigned* p) {
    unsigned v;
    asm volatile("ld.global.acquire.gpu.u32 %0, [%1];" : "=r"(v) : "l"(p));
    return v;
}
__device__ __forceinline__ void st_rel(unsigned* p, unsigned v) {
    asm volatile("st.global.release.gpu.u32 [%0], %1;" :: "l"(p), "r"(v));
}
__device__ __forceinline__ unsigned atom_add_rel(unsigned* p, unsigned v) {
    unsigned old;
    asm volatile("atom.add.release.gpu.u32 %0, [%1], %2;"
                 : "=r"(old) : "l"(p), "r"(v) : "memory");
    return old;
}
__device__ __forceinline__ float tanh_fast(float x) {
    float y;
    asm("tanh.approx.f32 %0, %1;" : "=f"(y) : "f"(x));
    return y;
}
__device__ __forceinline__ float sigmoid_fast(float x) {
    return fmaf(0.5f, tanh_fast(0.5f * x), 0.5f);
}
__device__ __forceinline__ void ldsm4(uint32_t r[4], uint32_t addr) {
    asm volatile("ldmatrix.sync.aligned.m8n8.x4.shared.b16 {%0,%1,%2,%3}, [%4];"
                 : "=r"(r[0]), "=r"(r[1]), "=r"(r[2]), "=r"(r[3]) : "r"(addr));
}
__device__ __forceinline__ void mma16816(float d[4], const uint32_t a[4],
                                         uint32_t b0, uint32_t b1) {
    asm volatile(
        "mma.sync.aligned.m16n8k16.row.col.f32.bf16.bf16.f32 "
        "{%0,%1,%2,%3}, {%4,%5,%6,%7}, {%8,%9}, {%0,%1,%2,%3};"
        : "+f"(d[0]), "+f"(d[1]), "+f"(d[2]), "+f"(d[3])
        : "r"(a[0]), "r"(a[1]), "r"(a[2]), "r"(a[3]), "r"(b0), "r"(b1));
}
__device__ __forceinline__ void split_bf16(float v, __nv_bfloat16& h, __nv_bfloat16& l) {
    h = __float2bfloat16_rn(v);
    l = __float2bfloat16_rn(v - __bfloat162float(h));
}
__device__ __forceinline__ void mbar_init(uint32_t a, uint32_t cnt) {
    asm volatile("mbarrier.init.shared.b64 [%0], %1;" :: "r"(a), "r"(cnt) : "memory");
}
__device__ __forceinline__ void mbar_expect_tx(uint32_t a, uint32_t tx) {
    asm volatile("mbarrier.arrive.expect_tx.shared.b64 _, [%0], %1;"
                 :: "r"(a), "r"(tx) : "memory");
}
__device__ __forceinline__ void mbar_wait(uint32_t a, uint32_t ph) {
    asm volatile(
        "{\n\t.reg .pred P;\n\t"
        "W_%=:\n\t"
        "mbarrier.try_wait.parity.acquire.cta.shared::cta.b64 P, [%0], %1, 0x989680;\n\t"
        "@!P bra W_%=;\n\t}"
        :: "r"(a), "r"(ph) : "memory");
}
__device__ __forceinline__ void bulk_cp(uint32_t dst, const void* src, uint32_t bytes,
                                        uint32_t mbar) {
    asm volatile(
        "cp.async.bulk.shared::cluster.global.mbarrier::complete_tx::bytes "
        "[%0], [%1], %2, [%3];"
        :: "r"(dst), "l"(src), "r"(bytes), "r"(mbar) : "memory");
}

// ---------------- dummy (profiler slot alignment) -----------------------------
__global__ void dummy_k() {}

// ---------------- init: h0 split-scatter + barrier reset ----------------------
__global__ void init_k(const float* __restrict__ enc_h) {
    int i = blockIdx.x * blockDim.x + threadIdx.x;   // 0 .. 65535
    int n = i & 511;
    int b = (i >> 9) & 63;
    int d = i >> 15;
    __nv_bfloat16 h, l;
    split_bf16(enc_h[b * 1024 + d * 512 + n], h, l);
    g_hh[0][d][b][n] = h;
    g_hl[0][d][b][n] = l;
    if (i < 64) { g_cnt[i] = 0; g_flag[i] = 0; }     // exact epochs per replay
}

// ---------------- precompute GEMM (fp32 FFMA2, proven) -----------------------
__global__ __launch_bounds__(256) void pre_k(const float* __restrict__ x,
                                             const float* __restrict__ Wf,
                                             const float* __restrict__ bf,
                                             const float* __restrict__ Wb,
                                             const float* __restrict__ bb_) {
    const int d = blockIdx.z;
    const float* __restrict__ W    = d ? Wb  : Wf;
    const float* __restrict__ bias = d ? bb_ : bf;

    __shared__ float As[128][36];
    __shared__ float Bs[64][36];

    const int tid = threadIdx.x;
    const int m0  = blockIdx.y * 128;
    const int j0  = blockIdx.x * 64;
    const int tm  = tid >> 4;
    const int tn  = tid & 15;

    u64 acc[8][4];
#pragma unroll
    for (int i = 0; i < 8; i++)
#pragma unroll
        for (int j = 0; j < 4; j++) acc[i][j] = 0ull;

    for (int k0 = 0; k0 < 512; k0 += 32) {
#pragma unroll
        for (int i = 0; i < 4; i++) {
            int q   = tid + i * 256;
            int row = q >> 3;
            int kq  = (q & 7) * 4;
            int m   = m0 + row;
            int t   = m >> 6;
            int b   = m & 63;
            int tx  = d ? (511 - t) : t;
            *(float4*)&As[row][kq] =
                *(const float4*)(x + ((size_t)b * 512 + tx) * 512 + k0 + kq);
        }
#pragma unroll
        for (int i = 0; i < 2; i++) {
            int q   = tid + i * 256;
            int row = q >> 3;
            int kq  = (q & 7) * 4;
            *(float4*)&Bs[row][kq] =
                *(const float4*)(W + (size_t)(j0 + row) * 512 + k0 + kq);
        }
        __syncthreads();

#pragma unroll
        for (int kk = 0; kk < 32; kk += 4) {
            ulonglong2 a2[8], b2[4];
#pragma unroll
            for (int i = 0; i < 8; i++)
                a2[i] = *(const ulonglong2*)&As[tm * 8 + i][kk];
#pragma unroll
            for (int j = 0; j < 4; j++)
                b2[j] = *(const ulonglong2*)&Bs[tn * 4 + j][kk];
#pragma unroll
            for (int i = 0; i < 8; i++)
#pragma unroll
                for (int j = 0; j < 4; j++) {
                    ffma2(acc[i][j], a2[i].x, b2[j].x);
                    ffma2(acc[i][j], a2[i].y, b2[j].y);
                }
        }
        __syncthreads();
    }

    float4 bb4 = *(const float4*)(bias + j0 + tn * 4);
#pragma unroll
    for (int i = 0; i < 8; i++) {
        int m = m0 + tm * 8 + i;
        int t = m >> 6;
        int b = m & 63;
        float4 o;
        o.x = hsum2(acc[i][0]) + bb4.x;
        o.y = hsum2(acc[i][1]) + bb4.y;
        o.z = hsum2(acc[i][2]) + bb4.z;
        o.w = hsum2(acc[i][3]) + bb4.w;
        *(float4*)(&g_pre[d][t][b][j0 + tn * 4]) = o;
    }
}

// ---------------- persistent HMMA recurrence (striped staging) ----------------
// 128 CTAs (1/SM), 256 threads. CTA = (d, 8 n-values); cols c = nl*4 + gate.
// h staged as 4 batch-stripes (hi+lo) with per-stripe mbarriers: warp w starts
// HMMA as soon as stripe (w&3) lands; remaining stripes stream under compute.
__global__ __launch_bounds__(256, 1) void persist_k(const float* __restrict__ Whf,
                                                    const float* __restrict__ Whb,
                                                    const float* __restrict__ enc_c,
                                                    float* __restrict__ out) {
    extern __shared__ char sm[];
    const uint32_t sb = (uint32_t)__cvta_generic_to_shared(sm);
    __nv_bfloat16* Wh_s = (__nv_bfloat16*)(sm + SM_WH);
    __nv_bfloat16* Wl_s = (__nv_bfloat16*)(sm + SM_WL);
    const uint32_t mbar = sb + SM_MB;

    const int d   = blockIdx.x >> 6;
    const int n0  = (blockIdx.x & 63) * 8;
    const int tid = threadIdx.x;
    const int w   = tid >> 5;               // warp 0..7
    const int l   = tid & 31;
    const float* __restrict__ W = d ? Whb : Whf;

    unsigned* cnt  = &g_cnt[d * 32];
    unsigned* flag = &g_flag[d * 32];

    // ---- convert resident W tile to split bf16 in smem (rows c = nl*4+gate) --
    for (int i = tid; i < 32 * 512; i += 256) {
        int r = i >> 9;
        int k = i & 511;
        int j = (r & 3) * 512 + n0 + (r >> 2);
        __nv_bfloat16 h, lo;
        split_bf16(W[(size_t)j * 512 + k], h, lo);
        Wh_s[r * HB + k] = h;
        Wl_s[r * HB + k] = lo;
    }

    // ---- per-lane geometry (verified R8 layout) ----
    const int m0 = (w & 3) * 16;             // batch stripe (also mbarrier id)
    const int jb = (w >> 2) * 16;            // col base (2 n8 tiles)
    const uint32_t aoff = (uint32_t)(((m0 + (l & 15)) * HB + ((l >> 4) * 8)) * 2);
    const uint32_t boff = (uint32_t)(((jb + ((l >> 4) & 1) * 8 + (l & 7)) * HB
                                      + (((l >> 3) & 1) * 8)) * 2);
    const uint32_t aHb = sb + SM_HH + aoff;
    const uint32_t aLb = sb + SM_HL + aoff;
    const uint32_t bHb = sb + SM_WH + boff;
    const uint32_t bLb = sb + SM_WL + boff;
    const uint32_t my_mbar = mbar + (uint32_t)((w & 3) * 8);

    const int b_out = m0 + (l >> 2) + ((l & 1) ? 8 : 0);
    const int nlb   = (jb >> 2) + ((l & 2) >> 1);

    float c_reg[2];
#pragma unroll
    for (int t2 = 0; t2 < 2; t2++)
        c_reg[t2] = enc_c[b_out * 1024 + d * 512 + n0 + nlb + 2 * t2];

    if (tid == 0)
        for (int s = 0; s < 4; s++) mbar_init(mbar + s * 8, 1);
    __syncthreads();

    // ---- g_pre register pipeline: load step 0 ----
    float pre_cur[2][4], pre_next[2][4];
#pragma unroll
    for (int t2 = 0; t2 < 2; t2++)
#pragma unroll
        for (int g = 0; g < 4; g++)
            pre_cur[t2][g] = __ldcs(&g_pre[d][0][b_out][g * 512 + n0 + nlb + 2 * t2]);

    int mph = 0;
    for (int t = 0; t < 512; t++) {
        const int ph = t & 1;

        // ---- stage h: 4 stripes x (hi+lo), one lane each ----
        if (tid < 4) {
            uint32_t mb = mbar + (uint32_t)(tid * 8);
            mbar_expect_tx(mb, 2 * STRIPE);
            bulk_cp(sb + SM_HH + tid * STRIPE, &g_hh[ph][d][tid * 16][0], STRIPE, mb);
            bulk_cp(sb + SM_HL + tid * STRIPE, &g_hl[ph][d][tid * 16][0], STRIPE, mb);
        }

        // ---- prefetch NEXT step's pre-activations (full-step lookahead) ----
        if (t + 1 < 512) {
#pragma unroll
            for (int t2 = 0; t2 < 2; t2++)
#pragma unroll
                for (int g = 0; g < 4; g++)
                    pre_next[t2][g] =
                        __ldcs(&g_pre[d][t + 1][b_out][g * 512 + n0 + nlb + 2 * t2]);
        }

        // ---- warp waits only for its own stripe ----
        mbar_wait(my_mbar, mph);
        mph ^= (w == 0 || true) ? 0 : 0;     // parity flips once per step (below)

        // ---- HMMA k-loop: 32 k16 steps, 6 independent acc chains ----
        float a_hh0[4] = {0, 0, 0, 0}, a_hh1[4] = {0, 0, 0, 0};
        float a_hl0[4] = {0, 0, 0, 0}, a_hl1[4] = {0, 0, 0, 0};
        float a_lh0[4] = {0, 0, 0, 0}, a_lh1[4] = {0, 0, 0, 0};
#pragma unroll 4
        for (int kk = 0; kk < 512; kk += 16) {
            uint32_t ah[4], al[4], bh[4], bl[4];
            ldsm4(ah, aHb + kk * 2);
            ldsm4(bh, bHb + kk * 2);
            ldsm4(al, aLb + kk * 2);
            ldsm4(bl, bLb + kk * 2);
            mma16816(a_hh0, ah, bh[0], bh[1]);
            mma16816(a_hh1, ah, bh[2], bh[3]);
            mma16816(a_hl0, ah, bl[0], bl[1]);
            mma16816(a_hl1, ah, bl[2], bl[3]);
            mma16816(a_lh0, al, bh[0], bh[1]);
            mma16816(a_lh1, al, bh[2], bh[3]);
        }
        mph ^= 1;                             // all stripes completed this step
        float acc0[4], acc1[4];
#pragma unroll
        for (int i = 0; i < 4; i++) {
            acc0[i] = a_hh0[i] + a_hl0[i] + a_lh0[i];
            acc1[i] = a_hh1[i] + a_hl1[i] + a_lh1[i];
        }

        // ---- gate exchange + fused epilogue (verified R8 pattern) ----
        const int odd = l & 1;
        const int tout = d ? (511 - t) : t;
        float* accs[2] = {acc0, acc1};
#pragma unroll
        for (int t2 = 0; t2 < 2; t2++) {
            float* a = accs[t2];
            float r0 = __shfl_xor_sync(0xFFFFFFFFu, odd ? a[0] : a[2], 1);
            float r1 = __shfl_xor_sync(0xFFFFFFFFu, odd ? a[1] : a[3], 1);
            float g0 = odd ? r0 : a[0];
            float g1 = odd ? r1 : a[1];
            float g2 = odd ? a[2] : r0;
            float g3 = odd ? a[3] : r1;

            float gi = pre_cur[t2][0] + g0;
            float gf = pre_cur[t2][1] + g1;
            float gg = pre_cur[t2][2] + g2;
            float go = pre_cur[t2][3] + g3;
            float si = sigmoid_fast(gi);
            float sf = sigmoid_fast(gf);
            float tg = tanh_fast(gg);
            float so = sigmoid_fast(go);
            float c  = sf * c_reg[t2] + si * tg;
            float h  = so * tanh_fast(c);
            c_reg[t2] = c;

            const int n = n0 + nlb + 2 * t2;
            __nv_bfloat16 hh, hl;
            split_bf16(h, hh, hl);
            g_hh[ph ^ 1][d][b_out][n] = hh;
            g_hl[ph ^ 1][d][b_out][n] = hl;
            __stcs(&out[((size_t)b_out * 512 + tout) * 1024 + d * 512 + n], h);
            if (t == 511) {
                __stcs(&out[33554432 + b_out * 1024 + d * 512 + n], h);
                __stcs(&out[33554432 + 65536 + b_out * 1024 + d * 512 + n], c);
            }
        }

        // ---- rotate pre pipeline ----
#pragma unroll
        for (int t2 = 0; t2 < 2; t2++)
#pragma unroll
            for (int g = 0; g < 4; g++) pre_cur[t2][g] = pre_next[t2][g];

        // ---- per-direction grid barrier: release-arrive + read-only flag ----
        if (t < 511) {
            __syncthreads();                 // all CTA h-writes done (cta scope)
            if (tid == 0) {
                unsigned ticket = atom_add_rel(cnt, 1u);   // gpu-scope release
                unsigned target = (unsigned)(t + 1);
                if ((ticket & 63u) == 63u) {
                    st_rel(flag, target);                  // publish epoch
                } else {
                    while (ld_acq(flag) < target) {}       // poll read-only line
                }
            }
            __syncthreads();
        }
    }
}

// ---------------- launch -----------------------------------------------------
extern "C" void kernel_launch(void* const* d_in, const int* in_sizes, int n_in,
                              void* d_out, int out_size) {
    const float* x     = (const float*)d_in[0];
    const float* enc_h = (const float*)d_in[1];
    const float* enc_c = (const float*)d_in[2];
    const float* Wih_f = (const float*)d_in[3];
    const float* Whh_f = (const float*)d_in[4];
    const float* b_f   = (const float*)d_in[5];
    const float* Wih_b = (const float*)d_in[6];
    const float* Whh_b = (const float*)d_in[7];
    const float* b_b   = (const float*)d_in[8];
    float* out = (float*)d_out;

    cudaFuncSetAttribute(persist_k, cudaFuncAttributeMaxDynamicSharedMemorySize,
                         PERSIST_SMEM);

    dummy_k<<<1, 32>>>();                  // slot alignment: slot5 = persist_k
    init_k<<<256, 256>>>(enc_h);

    dim3 gA(32, 256, 2);
    pre_k<<<gA, 256>>>(x, Wih_f, b_f, Wih_b, b_b);

    persist_k<<<NCTA, 256, PERSIST_SMEM>>>(Whh_f, Whh_b, enc_c, out);
}

// round 12
// speedup vs baseline: 1.0492x; 1.0492x over previous
#include <cuda_runtime.h>
#include <cuda_bf16.h>
#include <cstdint>

#define B_  64
#define T_  512
#define H_  512
#define NCTA 128

// padded h rows: 520 bf16 = 1040B -> conflict-free ldmatrix; whole [64][520]
// slice (66560B) is ONE contiguous bulk-copy block.
#define HB 520
#define HSLICE (B_ * HB * 2)                // 66560 bytes
#define SM_HH 0
#define SM_HL HSLICE                        // 66560
#define SM_WH (2 * HSLICE)                  // 133120
#define SM_WL (SM_WH + 32 * HB * 2)         // 166400
#define SM_MB (SM_WL + 32 * HB * 2)         // 199680 (mbarrier)
#define SM_HBUF (SM_MB + 64)                // h bounce buffers: 2 x [64][8] bf16
#define PERSIST_SMEM (SM_HBUF + 2048)       // 201792

typedef unsigned long long u64;

// ---------------- scratch (device globals; no runtime allocation) ----------
__device__ float g_pre[2][T_][B_][2048];            // x@Wih^T + bias  (512 MB)
__device__ __align__(16) __nv_bfloat16 g_hh[2][2][B_][HB];   // h hi (padded rows)
__device__ __align__(16) __nv_bfloat16 g_hl[2][2][B_][HB];   // h lo
__device__ unsigned g_cnt[2 * 32];                  // per-dir arrival counter

// ---------------- helpers -----------------------------------------------------
__device__ __forceinline__ void ffma2(u64& d, u64 a, u64 b) {
    asm("fma.rn.f32x2 %0, %1, %2, %0;" : "+l"(d) : "l"(a), "l"(b));
}
__device__ __forceinline__ float hsum2(u64 v) {
    float lo, hi;
    asm("mov.b64 {%0,%1}, %2;" : "=f"(lo), "=f"(hi) : "l"(v));
    return lo + hi;
}
__device__ __forceinline__ unsigned ld_acq(const unsigned* p) {
    unsigned v;
    asm volatile("ld.global.acquire.gpu.u32 %0, [%1];" : "=r"(v) : "l"(p));
    return v;
}
__device__ __forceinline__ unsigned atom_add_rel(unsigned* p, unsigned v) {
    unsigned old;
    asm volatile("atom.add.release.gpu.u32 %0, [%1], %2;"
                 : "=r"(old) : "l"(p), "r"(v) : "memory");
    return old;
}
__device__ __forceinline__ float tanh_fast(float x) {
    float y;
    asm("tanh.approx.f32 %0, %1;" : "=f"(y) : "f"(x));
    return y;
}
__device__ __forceinline__ float sigmoid_fast(float x) {
    return fmaf(0.5f, tanh_fast(0.5f * x), 0.5f);
}
__device__ __forceinline__ void ldsm4(uint32_t r[4], uint32_t addr) {
    asm volatile("ldmatrix.sync.aligned.m8n8.x4.shared.b16 {%0,%1,%2,%3}, [%4];"
                 : "=r"(r[0]), "=r"(r[1]), "=r"(r[2]), "=r"(r[3]) : "r"(addr));
}
__device__ __forceinline__ void mma16816(float d[4], const uint32_t a[4],
                                         uint32_t b0, uint32_t b1) {
    asm volatile(
        "mma.sync.aligned.m16n8k16.row.col.f32.bf16.bf16.f32 "
        "{%0,%1,%2,%3}, {%4,%5,%6,%7}, {%8,%9}, {%0,%1,%2,%3};"
        : "+f"(d[0]), "+f"(d[1]), "+f"(d[2]), "+f"(d[3])
        : "r"(a[0]), "r"(a[1]), "r"(a[2]), "r"(a[3]), "r"(b0), "r"(b1));
}
__device__ __forceinline__ void split_bf16(float v, __nv_bfloat16& h, __nv_bfloat16& l) {
    h = __float2bfloat16_rn(v);
    l = __float2bfloat16_rn(v - __bfloat162float(h));
}
__device__ __forceinline__ void mbar_init(uint32_t a, uint32_t cnt) {
    asm volatile("mbarrier.init.shared.b64 [%0], %1;" :: "r"(a), "r"(cnt) : "memory");
}
__device__ __forceinline__ void mbar_expect_tx(uint32_t a, uint32_t tx) {
    asm volatile("mbarrier.arrive.expect_tx.shared.b64 _, [%0], %1;"
                 :: "r"(a), "r"(tx) : "memory");
}
__device__ __forceinline__ void mbar_wait(uint32_t a, uint32_t ph) {
    asm volatile(
        "{\n\t.reg .pred P;\n\t"
        "W_%=:\n\t"
        "mbarrier.try_wait.parity.acquire.cta.shared::cta.b64 P, [%0], %1, 0x989680;\n\t"
        "@!P bra W_%=;\n\t}"
        :: "r"(a), "r"(ph) : "memory");
}
__device__ __forceinline__ void bulk_cp(uint32_t dst, const void* src, uint32_t bytes,
                                        uint32_t mbar) {
    asm volatile(
        "cp.async.bulk.shared::cluster.global.mbarrier::complete_tx::bytes "
        "[%0], [%1], %2, [%3];"
        :: "r"(dst), "l"(src), "r"(bytes), "r"(mbar) : "memory");
}

// ---------------- dummy (profiler slot alignment) -----------------------------
__global__ void dummy_k() {}

// ---------------- init: h0 split-scatter + barrier reset ----------------------
__global__ void init_k(const float* __restrict__ enc_h) {
    int i = blockIdx.x * blockDim.x + threadIdx.x;   // 0 .. 65535
    int n = i & 511;
    int b = (i >> 9) & 63;
    int d = i >> 15;
    __nv_bfloat16 h, l;
    split_bf16(enc_h[b * 1024 + d * 512 + n], h, l);
    g_hh[0][d][b][n] = h;
    g_hl[0][d][b][n] = l;
    if (i < 64) g_cnt[i] = 0;                        // exact epochs per replay
}

// ---------------- precompute GEMM (fp32 FFMA2, proven) -----------------------
__global__ __launch_bounds__(256) void pre_k(const float* __restrict__ x,
                                             const float* __restrict__ Wf,
                                             const float* __restrict__ bf,
                                             const float* __restrict__ Wb,
                                             const float* __restrict__ bb_) {
    const int d = blockIdx.z;
    const float* __restrict__ W    = d ? Wb  : Wf;
    const float* __restrict__ bias = d ? bb_ : bf;

    __shared__ float As[128][36];
    __shared__ float Bs[64][36];

    const int tid = threadIdx.x;
    const int m0  = blockIdx.y * 128;
    const int j0  = blockIdx.x * 64;
    const int tm  = tid >> 4;
    const int tn  = tid & 15;

    u64 acc[8][4];
#pragma unroll
    for (int i = 0; i < 8; i++)
#pragma unroll
        for (int j = 0; j < 4; j++) acc[i][j] = 0ull;

    for (int k0 = 0; k0 < 512; k0 += 32) {
#pragma unroll
        for (int i = 0; i < 4; i++) {
            int q   = tid + i * 256;
            int row = q >> 3;
            int kq  = (q & 7) * 4;
            int m   = m0 + row;
            int t   = m >> 6;
            int b   = m & 63;
            int tx  = d ? (511 - t) : t;
            *(float4*)&As[row][kq] =
                *(const float4*)(x + ((size_t)b * 512 + tx) * 512 + k0 + kq);
        }
#pragma unroll
        for (int i = 0; i < 2; i++) {
            int q   = tid + i * 256;
            int row = q >> 3;
            int kq  = (q & 7) * 4;
            *(float4*)&Bs[row][kq] =
                *(const float4*)(W + (size_t)(j0 + row) * 512 + k0 + kq);
        }
        __syncthreads();

#pragma unroll
        for (int kk = 0; kk < 32; kk += 4) {
            ulonglong2 a2[8], b2[4];
#pragma unroll
            for (int i = 0; i < 8; i++)
                a2[i] = *(const ulonglong2*)&As[tm * 8 + i][kk];
#pragma unroll
            for (int j = 0; j < 4; j++)
                b2[j] = *(const ulonglong2*)&Bs[tn * 4 + j][kk];
#pragma unroll
            for (int i = 0; i < 8; i++)
#pragma unroll
                for (int j = 0; j < 4; j++) {
                    ffma2(acc[i][j], a2[i].x, b2[j].x);
                    ffma2(acc[i][j], a2[i].y, b2[j].y);
                }
        }
        __syncthreads();
    }

    float4 bb4 = *(const float4*)(bias + j0 + tn * 4);
#pragma unroll
    for (int i = 0; i < 8; i++) {
        int m = m0 + tm * 8 + i;
        int t = m >> 6;
        int b = m & 63;
        float4 o;
        o.x = hsum2(acc[i][0]) + bb4.x;
        o.y = hsum2(acc[i][1]) + bb4.y;
        o.z = hsum2(acc[i][2]) + bb4.z;
        o.w = hsum2(acc[i][3]) + bb4.w;
        *(float4*)(&g_pre[d][t][b][j0 + tn * 4]) = o;
    }
}

// ---------------- persistent HMMA recurrence (lean critical path) -------------
// 128 CTAs (1/SM), 256 threads. CTA = (d, 8 n-values); cols c = nl*4 + gate.
// Critical path per step: mma -> h to smem -> 128 coalesced 16B stores ->
// release-arrive -> poll -> issue next bulk copy. `out` stores happen AFTER
// the arrival, overlapped with the TMA window.
__global__ __launch_bounds__(256, 1) void persist_k(const float* __restrict__ Whf,
                                                    const float* __restrict__ Whb,
                                                    const float* __restrict__ enc_c,
                                                    float* __restrict__ out) {
    extern __shared__ char sm[];
    const uint32_t sb = (uint32_t)__cvta_generic_to_shared(sm);
    __nv_bfloat16* Wh_s = (__nv_bfloat16*)(sm + SM_WH);
    __nv_bfloat16* Wl_s = (__nv_bfloat16*)(sm + SM_WL);
    __nv_bfloat16 (*hb_h)[8] = (__nv_bfloat16(*)[8])(sm + SM_HBUF);          // [64][8]
    __nv_bfloat16 (*hb_l)[8] = (__nv_bfloat16(*)[8])(sm + SM_HBUF + 1024);   // [64][8]
    const uint32_t mbar = sb + SM_MB;

    const int d   = blockIdx.x >> 6;
    const int n0  = (blockIdx.x & 63) * 8;
    const int tid = threadIdx.x;
    const int w   = tid >> 5;               // warp 0..7
    const int l   = tid & 31;
    const float* __restrict__ W = d ? Whb : Whf;

    unsigned* cnt = &g_cnt[d * 32];

    // ---- convert resident W tile to split bf16 in smem (rows c = nl*4+gate) --
    for (int i = tid; i < 32 * 512; i += 256) {
        int r = i >> 9;
        int k = i & 511;
        int j = (r & 3) * 512 + n0 + (r >> 2);
        __nv_bfloat16 h, lo;
        split_bf16(W[(size_t)j * 512 + k], h, lo);
        Wh_s[r * HB + k] = h;
        Wl_s[r * HB + k] = lo;
    }

    // ---- per-lane geometry (verified R8 layout) ----
    const int m0 = (w & 3) * 16;             // batch stripe
    const int jb = (w >> 2) * 16;            // col base (2 n8 tiles)
    const uint32_t aoff = (uint32_t)(((m0 + (l & 15)) * HB + ((l >> 4) * 8)) * 2);
    const uint32_t boff = (uint32_t)(((jb + ((l >> 4) & 1) * 8 + (l & 7)) * HB
                                      + (((l >> 3) & 1) * 8)) * 2);
    const uint32_t aHb = sb + SM_HH + aoff;
    const uint32_t aLb = sb + SM_HL + aoff;
    const uint32_t bHb = sb + SM_WH + boff;
    const uint32_t bLb = sb + SM_WL + boff;

    const int b_out = m0 + (l >> 2) + ((l & 1) ? 8 : 0);
    const int nlb   = (jb >> 2) + ((l & 2) >> 1);

    float c_reg[2];
#pragma unroll
    for (int t2 = 0; t2 < 2; t2++)
        c_reg[t2] = enc_c[b_out * 1024 + d * 512 + n0 + nlb + 2 * t2];

    if (tid == 0) mbar_init(mbar, 1);
    __syncthreads();

    // ---- g_pre register pipeline: load step 0; issue copy for step 0 ----
    if (tid == 0) {
        mbar_expect_tx(mbar, 2 * HSLICE);
        bulk_cp(sb + SM_HH, &g_hh[0][d][0][0], HSLICE, mbar);
        bulk_cp(sb + SM_HL, &g_hl[0][d][0][0], HSLICE, mbar);
    }
    float pre_cur[2][4], pre_next[2][4];
#pragma unroll
    for (int t2 = 0; t2 < 2; t2++)
#pragma unroll
        for (int g = 0; g < 4; g++)
            pre_cur[t2][g] = __ldcs(&g_pre[d][0][b_out][g * 512 + n0 + nlb + 2 * t2]);

    int mph = 0;
    for (int t = 0; t < 512; t++) {
        const int ph = t & 1;

        // ---- prefetch NEXT step's pre-activations (hidden under wait) ----
        if (t + 1 < 512) {
#pragma unroll
            for (int t2 = 0; t2 < 2; t2++)
#pragma unroll
                for (int g = 0; g < 4; g++)
                    pre_next[t2][g] =
                        __ldcs(&g_pre[d][t + 1][b_out][g * 512 + n0 + nlb + 2 * t2]);
        }

        mbar_wait(mbar, mph);
        mph ^= 1;

        // ---- HMMA k-loop: 32 k16 steps, 6 independent acc chains ----
        float a_hh0[4] = {0, 0, 0, 0}, a_hh1[4] = {0, 0, 0, 0};
        float a_hl0[4] = {0, 0, 0, 0}, a_hl1[4] = {0, 0, 0, 0};
        float a_lh0[4] = {0, 0, 0, 0}, a_lh1[4] = {0, 0, 0, 0};
#pragma unroll 4
        for (int kk = 0; kk < 512; kk += 16) {
            uint32_t ah[4], al[4], bh[4], bl[4];
            ldsm4(ah, aHb + kk * 2);
            ldsm4(bh, bHb + kk * 2);
            ldsm4(al, aLb + kk * 2);
            ldsm4(bl, bLb + kk * 2);
            mma16816(a_hh0, ah, bh[0], bh[1]);
            mma16816(a_hh1, ah, bh[2], bh[3]);
            mma16816(a_hl0, ah, bl[0], bl[1]);
            mma16816(a_hl1, ah, bl[2], bl[3]);
            mma16816(a_lh0, al, bh[0], bh[1]);
            mma16816(a_lh1, al, bh[2], bh[3]);
        }
        float acc0[4], acc1[4];
#pragma unroll
        for (int i = 0; i < 4; i++) {
            acc0[i] = a_hh0[i] + a_hl0[i] + a_lh0[i];
            acc1[i] = a_hh1[i] + a_hl1[i] + a_lh1[i];
        }

        // ---- gates: compute h,c; stage h into smem bounce buffer ----
        const int odd = l & 1;
        float h_res[2];
        float* accs[2] = {acc0, acc1};
#pragma unroll
        for (int t2 = 0; t2 < 2; t2++) {
            float* a = accs[t2];
            float r0 = __shfl_xor_sync(0xFFFFFFFFu, odd ? a[0] : a[2], 1);
            float r1 = __shfl_xor_sync(0xFFFFFFFFu, odd ? a[1] : a[3], 1);
            float g0 = odd ? r0 : a[0];
            float g1 = odd ? r1 : a[1];
            float g2 = odd ? a[2] : r0;
            float g3 = odd ? a[3] : r1;

            float gi = pre_cur[t2][0] + g0;
            float gf = pre_cur[t2][1] + g1;
            float gg = pre_cur[t2][2] + g2;
            float go = pre_cur[t2][3] + g3;
            float si = sigmoid_fast(gi);
            float sf = sigmoid_fast(gf);
            float tg = tanh_fast(gg);
            float so = sigmoid_fast(go);
            float c  = sf * c_reg[t2] + si * tg;
            float h  = so * tanh_fast(c);
            c_reg[t2] = c;
            h_res[t2] = h;

            __nv_bfloat16 hh, hl;
            split_bf16(h, hh, hl);
            hb_h[b_out][nlb + 2 * t2] = hh;
            hb_l[b_out][nlb + 2 * t2] = hl;
        }
        __syncthreads();

        // ---- coalesced h publication: 128 x 16B vector stores ----
        if (tid < 128) {
            int row = tid & 63;
            if (tid < 64)
                *(uint4*)&g_hh[ph ^ 1][d][row][n0] = *(const uint4*)&hb_h[row][0];
            else
                *(uint4*)&g_hl[ph ^ 1][d][row][n0] = *(const uint4*)&hb_l[row][0];
        }

        // ---- barrier arrive + next-copy issue (critical path) ----
        if (t < 511) {
            __syncthreads();                 // h stores issued by all warps
            if (tid == 0) {
                atom_add_rel(cnt, 1u);                     // gpu-scope release
                unsigned target = 64u * (unsigned)(t + 1);
                while (ld_acq(cnt) < target) {}            // absolute epoch
                mbar_expect_tx(mbar, 2 * HSLICE);          // issue copy for t+1
                bulk_cp(sb + SM_HH, &g_hh[(ph ^ 1)][d][0][0], HSLICE, mbar);
                bulk_cp(sb + SM_HL, &g_hl[(ph ^ 1)][d][0][0], HSLICE, mbar);
            }
            __syncthreads();
        }

        // ---- out stores: OFF the critical path (overlap TMA window) ----
        const int tout = d ? (511 - t) : t;
#pragma unroll
        for (int t2 = 0; t2 < 2; t2++) {
            const int n = n0 + nlb + 2 * t2;
            __stcs(&out[((size_t)b_out * 512 + tout) * 1024 + d * 512 + n], h_res[t2]);
            if (t == 511) {
                __stcs(&out[33554432 + b_out * 1024 + d * 512 + n], h_res[t2]);
                __stcs(&out[33554432 + 65536 + b_out * 1024 + d * 512 + n], c_reg[t2]);
            }
        }

        // ---- rotate pre pipeline ----
#pragma unroll
        for (int t2 = 0; t2 < 2; t2++)
#pragma unroll
            for (int g = 0; g < 4; g++) pre_cur[t2][g] = pre_next[t2][g];
    }
}

// ---------------- launch -----------------------------------------------------
extern "C" void kernel_launch(void* const* d_in, const int* in_sizes, int n_in,
                              void* d_out, int out_size) {
    const float* x     = (const float*)d_in[0];
    const float* enc_h = (const float*)d_in[1];
    const float* enc_c = (const float*)d_in[2];
    const float* Wih_f = (const float*)d_in[3];
    const float* Whh_f = (const float*)d_in[4];
    const float* b_f   = (const float*)d_in[5];
    const float* Wih_b = (const float*)d_in[6];
    const float* Whh_b = (const float*)d_in[7];
    const float* b_b   = (const float*)d_in[8];
    float* out = (float*)d_out;

    cudaFuncSetAttribute(persist_k, cudaFuncAttributeMaxDynamicSharedMemorySize,
                         PERSIST_SMEM);

    dummy_k<<<1, 32>>>();                  // slot alignment: slot5 = persist_k
    init_k<<<256, 256>>>(enc_h);

    dim3 gA(32, 256, 2);
    pre_k<<<gA, 256>>>(x, Wih_f, b_f, Wih_b, b_b);

    persist_k<<<NCTA, 256, PERSIST_SMEM>>>(Whh_f, Whh_b, enc_c, out);
}

// round 13
// speedup vs baseline: 1.1161x; 1.0638x over previous
#include <cuda_runtime.h>
#include <cuda_bf16.h>
#include <cuda_fp16.h>
#include <cstdint>

#define B_  64
#define T_  512
#define H_  512
#define NCTA 128

// padded h rows: 520 fp16 = 1040B -> conflict-free ldmatrix; whole [64][520]
// slice (66560B) is ONE contiguous bulk-copy block.
#define HB 520
#define HSLICE (B_ * HB * 2)                // 66560 bytes
#define SM_H  0
#define SM_WH HSLICE                        // 66560
#define SM_WL (SM_WH + 32 * HB * 2)         // 99840
#define SM_MB (SM_WL + 32 * HB * 2)         // 133120 (mbarrier)
#define SM_HBUF (SM_MB + 64)                // h bounce buffer: [64][8] fp16
#define PERSIST_SMEM (SM_HBUF + 1024)       // 134208

typedef unsigned long long u64;

// ---------------- scratch (device globals; no runtime allocation) ----------
__device__ float g_pre[2][T_][B_][2048];            // x@Wih^T + bias  (512 MB)
__device__ __align__(16) __half g_hf[2][2][B_][HB]; // h fp16, ping-pong (padded)
__device__ unsigned g_cnt[2 * 32];                  // per-dir arrival counter

// ---------------- helpers -----------------------------------------------------
__device__ __forceinline__ void ffma2(u64& d, u64 a, u64 b) {
    asm("fma.rn.f32x2 %0, %1, %2, %0;" : "+l"(d) : "l"(a), "l"(b));
}
__device__ __forceinline__ float hsum2(u64 v) {
    float lo, hi;
    asm("mov.b64 {%0,%1}, %2;" : "=f"(lo), "=f"(hi) : "l"(v));
    return lo + hi;
}
__device__ __forceinline__ unsigned ld_acq(const unsigned* p) {
    unsigned v;
    asm volatile("ld.global.acquire.gpu.u32 %0, [%1];" : "=r"(v) : "l"(p));
    return v;
}
__device__ __forceinline__ unsigned atom_add_rel(unsigned* p, unsigned v) {
    unsigned old;
    asm volatile("atom.add.release.gpu.u32 %0, [%1], %2;"
                 : "=r"(old) : "l"(p), "r"(v) : "memory");
    return old;
}
__device__ __forceinline__ float tanh_fast(float x) {
    float y;
    asm("tanh.approx.f32 %0, %1;" : "=f"(y) : "f"(x));
    return y;
}
__device__ __forceinline__ float sigmoid_fast(float x) {
    return fmaf(0.5f, tanh_fast(0.5f * x), 0.5f);
}
__device__ __forceinline__ void ldsm4(uint32_t r[4], uint32_t addr) {
    asm volatile("ldmatrix.sync.aligned.m8n8.x4.shared.b16 {%0,%1,%2,%3}, [%4];"
                 : "=r"(r[0]), "=r"(r[1]), "=r"(r[2]), "=r"(r[3]) : "r"(addr));
}
__device__ __forceinline__ void mma16816h(float d[4], const uint32_t a[4],
                                          uint32_t b0, uint32_t b1) {
    asm volatile(
        "mma.sync.aligned.m16n8k16.row.col.f32.f16.f16.f32 "
        "{%0,%1,%2,%3}, {%4,%5,%6,%7}, {%8,%9}, {%0,%1,%2,%3};"
        : "+f"(d[0]), "+f"(d[1]), "+f"(d[2]), "+f"(d[3])
        : "r"(a[0]), "r"(a[1]), "r"(a[2]), "r"(a[3]), "r"(b0), "r"(b1));
}
__device__ __forceinline__ void mbar_init(uint32_t a, uint32_t cnt) {
    asm volatile("mbarrier.init.shared.b64 [%0], %1;" :: "r"(a), "r"(cnt) : "memory");
}
__device__ __forceinline__ void mbar_expect_tx(uint32_t a, uint32_t tx) {
    asm volatile("mbarrier.arrive.expect_tx.shared.b64 _, [%0], %1;"
                 :: "r"(a), "r"(tx) : "memory");
}
__device__ __forceinline__ void mbar_wait(uint32_t a, uint32_t ph) {
    asm volatile(
        "{\n\t.reg .pred P;\n\t"
        "W_%=:\n\t"
        "mbarrier.try_wait.parity.acquire.cta.shared::cta.b64 P, [%0], %1, 0x989680;\n\t"
        "@!P bra W_%=;\n\t}"
        :: "r"(a), "r"(ph) : "memory");
}
__device__ __forceinline__ void bulk_cp(uint32_t dst, const void* src, uint32_t bytes,
                                        uint32_t mbar) {
    asm volatile(
        "cp.async.bulk.shared::cluster.global.mbarrier::complete_tx::bytes "
        "[%0], [%1], %2, [%3];"
        :: "r"(dst), "l"(src), "r"(bytes), "r"(mbar) : "memory");
}

// ---------------- dummy (profiler slot alignment) -----------------------------
__global__ void dummy_k() {}

// ---------------- init: h0 fp16 scatter + barrier reset ------------------------
__global__ void init_k(const float* __restrict__ enc_h) {
    int i = blockIdx.x * blockDim.x + threadIdx.x;   // 0 .. 65535
    int n = i & 511;
    int b = (i >> 9) & 63;
    int d = i >> 15;
    g_hf[0][d][b][n] = __float2half_rn(enc_h[b * 1024 + d * 512 + n]);
    if (i < 64) g_cnt[i] = 0;                        // exact epochs per replay
}

// ---------------- precompute GEMM (fp32 FFMA2, proven) -----------------------
__global__ __launch_bounds__(256) void pre_k(const float* __restrict__ x,
                                             const float* __restrict__ Wf,
                                             const float* __restrict__ bf,
                                             const float* __restrict__ Wb,
                                             const float* __restrict__ bb_) {
    const int d = blockIdx.z;
    const float* __restrict__ W    = d ? Wb  : Wf;
    const float* __restrict__ bias = d ? bb_ : bf;

    __shared__ float As[128][36];
    __shared__ float Bs[64][36];

    const int tid = threadIdx.x;
    const int m0  = blockIdx.y * 128;
    const int j0  = blockIdx.x * 64;
    const int tm  = tid >> 4;
    const int tn  = tid & 15;

    u64 acc[8][4];
#pragma unroll
    for (int i = 0; i < 8; i++)
#pragma unroll
        for (int j = 0; j < 4; j++) acc[i][j] = 0ull;

    for (int k0 = 0; k0 < 512; k0 += 32) {
#pragma unroll
        for (int i = 0; i < 4; i++) {
            int q   = tid + i * 256;
            int row = q >> 3;
            int kq  = (q & 7) * 4;
            int m   = m0 + row;
            int t   = m >> 6;
            int b   = m & 63;
            int tx  = d ? (511 - t) : t;
            *(float4*)&As[row][kq] =
                *(const float4*)(x + ((size_t)b * 512 + tx) * 512 + k0 + kq);
        }
#pragma unroll
        for (int i = 0; i < 2; i++) {
            int q   = tid + i * 256;
            int row = q >> 3;
            int kq  = (q & 7) * 4;
            *(float4*)&Bs[row][kq] =
                *(const float4*)(W + (size_t)(j0 + row) * 512 + k0 + kq);
        }
        __syncthreads();

#pragma unroll
        for (int kk = 0; kk < 32; kk += 4) {
            ulonglong2 a2[8], b2[4];
#pragma unroll
            for (int i = 0; i < 8; i++)
                a2[i] = *(const ulonglong2*)&As[tm * 8 + i][kk];
#pragma unroll
            for (int j = 0; j < 4; j++)
                b2[j] = *(const ulonglong2*)&Bs[tn * 4 + j][kk];
#pragma unroll
            for (int i = 0; i < 8; i++)
#pragma unroll
                for (int j = 0; j < 4; j++) {
                    ffma2(acc[i][j], a2[i].x, b2[j].x);
                    ffma2(acc[i][j], a2[i].y, b2[j].y);
                }
        }
        __syncthreads();
    }

    float4 bb4 = *(const float4*)(bias + j0 + tn * 4);
#pragma unroll
    for (int i = 0; i < 8; i++) {
        int m = m0 + tm * 8 + i;
        int t = m >> 6;
        int b = m & 63;
        float4 o;
        o.x = hsum2(acc[i][0]) + bb4.x;
        o.y = hsum2(acc[i][1]) + bb4.y;
        o.z = hsum2(acc[i][2]) + bb4.z;
        o.w = hsum2(acc[i][3]) + bb4.w;
        *(float4*)(&g_pre[d][t][b][j0 + tn * 4]) = o;
    }
}

// ---------------- persistent HMMA recurrence (fp16 h, split-fp16 W) -----------
// 128 CTAs (1/SM), 256 threads. CTA = (d, 8 n-values); cols c = nl*4 + gate.
// h carried in fp16 (|h|<1 -> 2^-12 rel err); W in fp16 hi+lo -> 2-pass mma.
__global__ __launch_bounds__(256, 1) void persist_k(const float* __restrict__ Whf,
                                                    const float* __restrict__ Whb,
                                                    const float* __restrict__ enc_c,
                                                    float* __restrict__ out) {
    extern __shared__ char sm[];
    const uint32_t sb = (uint32_t)__cvta_generic_to_shared(sm);
    __half* Wh_s = (__half*)(sm + SM_WH);
    __half* Wl_s = (__half*)(sm + SM_WL);
    __half (*hb)[8] = (__half(*)[8])(sm + SM_HBUF);           // [64][8]
    const uint32_t mbar = sb + SM_MB;

    const int d   = blockIdx.x >> 6;
    const int n0  = (blockIdx.x & 63) * 8;
    const int tid = threadIdx.x;
    const int w   = tid >> 5;               // warp 0..7
    const int l   = tid & 31;
    const float* __restrict__ W = d ? Whb : Whf;

    unsigned* cnt = &g_cnt[d * 32];

    // ---- convert resident W tile to split fp16 in smem (rows c = nl*4+gate) --
    for (int i = tid; i < 32 * 512; i += 256) {
        int r = i >> 9;
        int k = i & 511;
        int j = (r & 3) * 512 + n0 + (r >> 2);
        float wv = W[(size_t)j * 512 + k];
        __half hi = __float2half_rn(wv);
        __half lo = __float2half_rn(wv - __half2float(hi));
        Wh_s[r * HB + k] = hi;
        Wl_s[r * HB + k] = lo;
    }

    // ---- per-lane geometry (verified R8 layout) ----
    const int m0 = (w & 3) * 16;             // batch stripe
    const int jb = (w >> 2) * 16;            // col base (2 n8 tiles)
    const uint32_t aoff = (uint32_t)(((m0 + (l & 15)) * HB + ((l >> 4) * 8)) * 2);
    const uint32_t boff = (uint32_t)(((jb + ((l >> 4) & 1) * 8 + (l & 7)) * HB
                                      + (((l >> 3) & 1) * 8)) * 2);
    const uint32_t aHb = sb + SM_H + aoff;
    const uint32_t bHb = sb + SM_WH + boff;
    const uint32_t bLb = sb + SM_WL + boff;

    const int b_out = m0 + (l >> 2) + ((l & 1) ? 8 : 0);
    const int nlb   = (jb >> 2) + ((l & 2) >> 1);

    float c_reg[2];
#pragma unroll
    for (int t2 = 0; t2 < 2; t2++)
        c_reg[t2] = enc_c[b_out * 1024 + d * 512 + n0 + nlb + 2 * t2];

    if (tid == 0) mbar_init(mbar, 1);
    __syncthreads();

    // ---- issue copy for step 0; prime g_pre register pipeline ----
    if (tid == 0) {
        mbar_expect_tx(mbar, HSLICE);
        bulk_cp(sb + SM_H, &g_hf[0][d][0][0], HSLICE, mbar);
    }
    float pre_cur[2][4], pre_next[2][4];
#pragma unroll
    for (int t2 = 0; t2 < 2; t2++)
#pragma unroll
        for (int g = 0; g < 4; g++)
            pre_cur[t2][g] = __ldcs(&g_pre[d][0][b_out][g * 512 + n0 + nlb + 2 * t2]);

    int mph = 0;
    for (int t = 0; t < 512; t++) {
        const int ph = t & 1;

        // ---- prefetch NEXT step's pre-activations (hidden under wait) ----
        if (t + 1 < 512) {
#pragma unroll
            for (int t2 = 0; t2 < 2; t2++)
#pragma unroll
                for (int g = 0; g < 4; g++)
                    pre_next[t2][g] =
                        __ldcs(&g_pre[d][t + 1][b_out][g * 512 + n0 + nlb + 2 * t2]);
        }

        mbar_wait(mbar, mph);
        mph ^= 1;

        // ---- HMMA k-loop: 32 k16 steps, 4 independent acc chains ----
        float a_h0[4] = {0, 0, 0, 0}, a_h1[4] = {0, 0, 0, 0};
        float a_l0[4] = {0, 0, 0, 0}, a_l1[4] = {0, 0, 0, 0};
#pragma unroll 4
        for (int kk = 0; kk < 512; kk += 16) {
            uint32_t ah[4], bh[4], bl[4];
            ldsm4(ah, aHb + kk * 2);
            ldsm4(bh, bHb + kk * 2);
            ldsm4(bl, bLb + kk * 2);
            mma16816h(a_h0, ah, bh[0], bh[1]);
            mma16816h(a_h1, ah, bh[2], bh[3]);
            mma16816h(a_l0, ah, bl[0], bl[1]);
            mma16816h(a_l1, ah, bl[2], bl[3]);
        }
        float acc0[4], acc1[4];
#pragma unroll
        for (int i = 0; i < 4; i++) {
            acc0[i] = a_h0[i] + a_l0[i];
            acc1[i] = a_h1[i] + a_l1[i];
        }

        // ---- gates: compute h,c; stage h into smem bounce buffer ----
        const int odd = l & 1;
        float h_res[2];
        float* accs[2] = {acc0, acc1};
#pragma unroll
        for (int t2 = 0; t2 < 2; t2++) {
            float* a = accs[t2];
            float r0 = __shfl_xor_sync(0xFFFFFFFFu, odd ? a[0] : a[2], 1);
            float r1 = __shfl_xor_sync(0xFFFFFFFFu, odd ? a[1] : a[3], 1);
            float g0 = odd ? r0 : a[0];
            float g1 = odd ? r1 : a[1];
            float g2 = odd ? a[2] : r0;
            float g3 = odd ? a[3] : r1;

            float gi = pre_cur[t2][0] + g0;
            float gf = pre_cur[t2][1] + g1;
            float gg = pre_cur[t2][2] + g2;
            float go = pre_cur[t2][3] + g3;
            float si = sigmoid_fast(gi);
            float sf = sigmoid_fast(gf);
            float tg = tanh_fast(gg);
            float so = sigmoid_fast(go);
            float c  = sf * c_reg[t2] + si * tg;
            float h  = so * tanh_fast(c);
            c_reg[t2] = c;
            h_res[t2] = h;

            hb[b_out][nlb + 2 * t2] = __float2half_rn(h);
        }
        __syncthreads();

        // ---- coalesced h publication: 64 x 16B vector stores ----
        if (tid < 64)
            *(uint4*)&g_hf[ph ^ 1][d][tid][n0] = *(const uint4*)&hb[tid][0];

        // ---- barrier arrive + next-copy issue (critical path) ----
        if (t < 511) {
            __syncthreads();                 // h stores issued by all warps
            if (tid == 0) {
                atom_add_rel(cnt, 1u);                     // gpu-scope release
                unsigned target = 64u * (unsigned)(t + 1);
                while (ld_acq(cnt) < target) {}            // absolute epoch
                mbar_expect_tx(mbar, HSLICE);              // issue copy for t+1
                bulk_cp(sb + SM_H, &g_hf[(ph ^ 1)][d][0][0], HSLICE, mbar);
            }
            __syncthreads();
        }

        // ---- out stores: OFF the critical path (overlap TMA window) ----
        const int tout = d ? (511 - t) : t;
#pragma unroll
        for (int t2 = 0; t2 < 2; t2++) {
            const int n = n0 + nlb + 2 * t2;
            __stcs(&out[((size_t)b_out * 512 + tout) * 1024 + d * 512 + n], h_res[t2]);
            if (t == 511) {
                __stcs(&out[33554432 + b_out * 1024 + d * 512 + n], h_res[t2]);
                __stcs(&out[33554432 + 65536 + b_out * 1024 + d * 512 + n], c_reg[t2]);
            }
        }

        // ---- rotate pre pipeline ----
#pragma unroll
        for (int t2 = 0; t2 < 2; t2++)
#pragma unroll
            for (int g = 0; g < 4; g++) pre_cur[t2][g] = pre_next[t2][g];
    }
}

// ---------------- launch -----------------------------------------------------
extern "C" void kernel_launch(void* const* d_in, const int* in_sizes, int n_in,
                              void* d_out, int out_size) {
    const float* x     = (const float*)d_in[0];
    const float* enc_h = (const float*)d_in[1];
    const float* enc_c = (const float*)d_in[2];
    const float* Wih_f = (const float*)d_in[3];
    const float* Whh_f = (const float*)d_in[4];
    const float* b_f   = (const float*)d_in[5];
    const float* Wih_b = (const float*)d_in[6];
    const float* Whh_b = (const float*)d_in[7];
    const float* b_b   = (const float*)d_in[8];
    float* out = (float*)d_out;

    cudaFuncSetAttribute(persist_k, cudaFuncAttributeMaxDynamicSharedMemorySize,
                         PERSIST_SMEM);

    dummy_k<<<1, 32>>>();                  // slot alignment: slot5 = persist_k
    init_k<<<256, 256>>>(enc_h);

    dim3 gA(32, 256, 2);
    pre_k<<<gA, 256>>>(x, Wih_f, b_f, Wih_b, b_b);

    persist_k<<<NCTA, 256, PERSIST_SMEM>>>(Whh_f, Whh_b, enc_c, out);
}

// round 14
// speedup vs baseline: 2.9866x; 2.6760x over previous
#include <cuda_runtime.h>
#include <cuda_fp16.h>
#include <cstdint>

#define B_  64
#define T_  512
#define H_  512
#define NCTA 128

// ---------------- persist smem layout (unchanged R13) -------------------------
#define HB 520
#define HSLICE (B_ * HB * 2)                // 66560 bytes
#define SM_H  0
#define SM_WH HSLICE                        // 66560
#define SM_WL (SM_WH + 32 * HB * 2)         // 99840
#define SM_MB (SM_WL + 32 * HB * 2)         // 133120 (mbarrier)
#define SM_HBUF (SM_MB + 64)                // h bounce buffer: [64][8] fp16
#define PERSIST_SMEM (SM_HBUF + 1024)       // 134208

// ---------------- pre_tc smem layout ------------------------------------------
#define PT_XS 0                              // [128][72] fp16 = 18432
#define PT_WH 18432                          // [64][72] fp16 = 9216
#define PT_WL 27648                          // [64][72] fp16 = 9216
#define PT_BUF 36864
#define PT_BIAS (2 * PT_BUF)                 // 73728 (+256)
#define PT_SMEM (PT_BIAS + 256)              // 73984

// ---------------- scratch (device globals; no runtime allocation) ----------
__device__ float g_pre[2][T_][B_][2048];            // x@Wih^T + bias  (512 MB)
__device__ __align__(16) __half g_hf[2][2][B_][HB]; // h fp16, ping-pong (padded)
__device__ unsigned g_cnt[2 * 32];                  // per-dir arrival counter
__device__ __align__(16) __half g_xh[32768 * 512];  // x fp16 [m=t*64+b][k] (32MB)
__device__ __align__(16) __half g_Wh[2 * 2048 * 512];  // Wih hi fp16
__device__ __align__(16) __half g_Wl[2 * 2048 * 512];  // Wih lo fp16

// ---------------- helpers -----------------------------------------------------
__device__ __forceinline__ unsigned ld_acq(const unsigned* p) {
    unsigned v;
    asm volatile("ld.global.acquire.gpu.u32 %0, [%1];" : "=r"(v) : "l"(p));
    return v;
}
__device__ __forceinline__ unsigned atom_add_rel(unsigned* p, unsigned v) {
    unsigned old;
    asm volatile("atom.add.release.gpu.u32 %0, [%1], %2;"
                 : "=r"(old) : "l"(p), "r"(v) : "memory");
    return old;
}
__device__ __forceinline__ float tanh_fast(float x) {
    float y;
    asm("tanh.approx.f32 %0, %1;" : "=f"(y) : "f"(x));
    return y;
}
__device__ __forceinline__ float sigmoid_fast(float x) {
    return fmaf(0.5f, tanh_fast(0.5f * x), 0.5f);
}
__device__ __forceinline__ void ldsm4(uint32_t r[4], uint32_t addr) {
    asm volatile("ldmatrix.sync.aligned.m8n8.x4.shared.b16 {%0,%1,%2,%3}, [%4];"
                 : "=r"(r[0]), "=r"(r[1]), "=r"(r[2]), "=r"(r[3]) : "r"(addr));
}
__device__ __forceinline__ void mma16816h(float d[4], const uint32_t a[4],
                                          uint32_t b0, uint32_t b1) {
    asm volatile(
        "mma.sync.aligned.m16n8k16.row.col.f32.f16.f16.f32 "
        "{%0,%1,%2,%3}, {%4,%5,%6,%7}, {%8,%9}, {%0,%1,%2,%3};"
        : "+f"(d[0]), "+f"(d[1]), "+f"(d[2]), "+f"(d[3])
        : "r"(a[0]), "r"(a[1]), "r"(a[2]), "r"(a[3]), "r"(b0), "r"(b1));
}
__device__ __forceinline__ void mbar_init(uint32_t a, uint32_t cnt) {
    asm volatile("mbarrier.init.shared.b64 [%0], %1;" :: "r"(a), "r"(cnt) : "memory");
}
__device__ __forceinline__ void mbar_expect_tx(uint32_t a, uint32_t tx) {
    asm volatile("mbarrier.arrive.expect_tx.shared.b64 _, [%0], %1;"
                 :: "r"(a), "r"(tx) : "memory");
}
__device__ __forceinline__ void mbar_wait(uint32_t a, uint32_t ph) {
    asm volatile(
        "{\n\t.reg .pred P;\n\t"
        "W_%=:\n\t"
        "mbarrier.try_wait.parity.acquire.cta.shared::cta.b64 P, [%0], %1, 0x989680;\n\t"
        "@!P bra W_%=;\n\t}"
        :: "r"(a), "r"(ph) : "memory");
}
__device__ __forceinline__ void bulk_cp(uint32_t dst, const void* src, uint32_t bytes,
                                        uint32_t mbar) {
    asm volatile(
        "cp.async.bulk.shared::cluster.global.mbarrier::complete_tx::bytes "
        "[%0], [%1], %2, [%3];"
        :: "r"(dst), "l"(src), "r"(bytes), "r"(mbar) : "memory");
}
__device__ __forceinline__ void cp_async16(unsigned saddr, const void* gptr) {
    asm volatile("cp.async.cg.shared.global [%0], [%1], 16;" :: "r"(saddr), "l"(gptr));
}
__device__ __forceinline__ void cp_commit() { asm volatile("cp.async.commit_group;"); }
__device__ __forceinline__ void cp_wait0()  { asm volatile("cp.async.wait_group 0;" ::: "memory"); }
__device__ __forceinline__ void cp_wait1()  { asm volatile("cp.async.wait_group 1;" ::: "memory"); }

// ---------------- dummy (profiler slot alignment) -----------------------------
__global__ void dummy_k() {}

// ---------------- init: h0 fp16 scatter + barrier reset ------------------------
__global__ void init_k(const float* __restrict__ enc_h) {
    int i = blockIdx.x * blockDim.x + threadIdx.x;   // 0 .. 65535
    int n = i & 511;
    int b = (i >> 9) & 63;
    int d = i >> 15;
    g_hf[0][d][b][n] = __float2half_rn(enc_h[b * 1024 + d * 512 + n]);
    if (i < 64) g_cnt[i] = 0;                        // exact epochs per replay
}

// ---------------- convert x -> fp16 [m=t*64+b][k] ------------------------------
__global__ __launch_bounds__(256) void cvtX_k(const float* __restrict__ x) {
    int idx = blockIdx.x * 256 + threadIdx.x;
    int e   = idx * 4;
    int b   = e >> 18;
    int rem = e & 262143;
    int t   = rem >> 9;
    int k   = rem & 511;
    float4 v = *(const float4*)(x + e);
    __half2* dp = (__half2*)&g_xh[((size_t)(t * 64 + b) << 9) + k];
    dp[0] = __floats2half2_rn(v.x, v.y);
    dp[1] = __floats2half2_rn(v.z, v.w);
}

// ---------------- convert Wih -> split fp16 ------------------------------------
__global__ __launch_bounds__(256) void cvtW_k(const float* __restrict__ Wf,
                                              const float* __restrict__ Wb) {
    int idx = blockIdx.x * 256 + threadIdx.x;
    int e   = idx * 4;
    int d   = e >> 20;
    int rem = e & 1048575;
    const float* src = d ? Wb : Wf;
    float4 v = *(const float4*)(src + rem);
    size_t a = (size_t)d * 1048576 + rem;
    float f[4] = {v.x, v.y, v.z, v.w};
    __half hi[4], lo[4];
#pragma unroll
    for (int i = 0; i < 4; i++) {
        hi[i] = __float2half_rn(f[i]);
        lo[i] = __float2half_rn(f[i] - __half2float(hi[i]));
    }
    __half2* dh = (__half2*)&g_Wh[a];
    __half2* dl = (__half2*)&g_Wl[a];
    dh[0] = __halves2half2(hi[0], hi[1]); dh[1] = __halves2half2(hi[2], hi[3]);
    dl[0] = __halves2half2(lo[0], lo[1]); dl[1] = __halves2half2(lo[2], lo[3]);
}

// ---------------- pre_tc: stage one 64-k chunk ---------------------------------
__device__ __forceinline__ void pre_stage(uint32_t sb, int buf, int k0, int t0,
                                          int j0, int d, int tid,
                                          const __half* Whg, const __half* Wlg) {
    uint32_t base = sb + buf * PT_BUF;
    // X: 128 rows x 64 k fp16 -> 1024 x 16B, 4 per thread
#pragma unroll
    for (int i = 0; i < 4; i++) {
        int q  = tid + i * 256;
        int r  = q >> 3;                       // 0..127
        int ko = (q & 7) * 8;                  // halfs
        int t  = t0 + (r >> 6);
        int tx = d ? (511 - t) : t;
        size_t grow = (size_t)(tx * 64 + (r & 63));
        cp_async16(base + PT_XS + (uint32_t)(r * 72 + ko) * 2,
                   g_xh + (grow << 9) + k0 + ko);
    }
    // Whi / Wlo: 64 rows x 64 k each -> 512 x 16B, 2 per thread each
#pragma unroll
    for (int i = 0; i < 2; i++) {
        int q  = tid + i * 256;
        int r  = q >> 3;                       // 0..63
        int ko = (q & 7) * 8;
        size_t src = ((size_t)(j0 + r) << 9) + k0 + ko;
        cp_async16(base + PT_WH + (uint32_t)(r * 72 + ko) * 2, Whg + src);
        cp_async16(base + PT_WL + (uint32_t)(r * 72 + ko) * 2, Wlg + src);
    }
}

// ---------------- precompute GEMM on tensor cores (fp16 2-pass) ---------------
// grid (32 j-tiles, 256 m-tiles, 2 dirs), 256 threads = 8 warps (2m x 4n).
// CTA: D[128 m, 64 j] = x[128,512] @ (Whi+Wlo)[64,512]^T + bias.
__global__ __launch_bounds__(256) void pre_tc(const float* __restrict__ bf,
                                              const float* __restrict__ bb_) {
    extern __shared__ char sm[];
    const uint32_t sb = (uint32_t)__cvta_generic_to_shared(sm);
    const int tid = threadIdx.x;
    const int w   = tid >> 5;
    const int l   = tid & 31;
    const int d   = blockIdx.z;
    const int j0  = blockIdx.x * 64;
    const int t0  = blockIdx.y * 2;            // 128 m rows = 2 t values
    const __half* Whg = g_Wh + (size_t)d * 1048576;
    const __half* Wlg = g_Wl + (size_t)d * 1048576;
    const float* bias = d ? bb_ : bf;

    float* bias_s = (float*)(sm + PT_BIAS);
    if (tid < 64) bias_s[tid] = bias[j0 + tid];

    const int wr = w >> 2;                     // m block (0..1)
    const int wc = w & 3;                      // n block (0..3)
    const uint32_t a_row = (uint32_t)(wr * 64 + (l & 15));
    const uint32_t a_col = (uint32_t)((l >> 4) * 8);
    const uint32_t b_row = (uint32_t)(wc * 16 + ((l >> 4) & 1) * 8 + (l & 7));
    const uint32_t b_col = (uint32_t)(((l >> 3) & 1) * 8);

    float acc[4][2][4];
#pragma unroll
    for (int i = 0; i < 4; i++)
#pragma unroll
        for (int j = 0; j < 2; j++)
#pragma unroll
            for (int q = 0; q < 4; q++) acc[i][j][q] = 0.f;

    pre_stage(sb, 0, 0, t0, j0, d, tid, Whg, Wlg);
    cp_commit();

    for (int c = 0; c < 8; c++) {
        if (c + 1 < 8) {
            pre_stage(sb, (c + 1) & 1, (c + 1) * 64, t0, j0, d, tid, Whg, Wlg);
            cp_commit();
            cp_wait1();
        } else {
            cp_wait0();
        }
        __syncthreads();
        uint32_t base = sb + (c & 1) * PT_BUF;
#pragma unroll
        for (int kk = 0; kk < 64; kk += 16) {
            uint32_t bh[4], bl[4], a[4][4];
            ldsm4(bh, base + PT_WH + (b_row * 72 + b_col + kk) * 2);
            ldsm4(bl, base + PT_WL + (b_row * 72 + b_col + kk) * 2);
#pragma unroll
            for (int i = 0; i < 4; i++)
                ldsm4(a[i], base + PT_XS + ((a_row + i * 16) * 72 + a_col + kk) * 2);
#pragma unroll
            for (int i = 0; i < 4; i++) {
                mma16816h(acc[i][0], a[i], bh[0], bh[1]);
                mma16816h(acc[i][1], a[i], bh[2], bh[3]);
            }
#pragma unroll
            for (int i = 0; i < 4; i++) {
                mma16816h(acc[i][0], a[i], bl[0], bl[1]);
                mma16816h(acc[i][1], a[i], bl[2], bl[3]);
            }
        }
        __syncthreads();
    }

    // epilogue: lane l of tile (i,jt): rows (l>>2)+{0,8}, cols 2(l&3)+{0,1}
#pragma unroll
    for (int i = 0; i < 4; i++)
#pragma unroll
        for (int jt = 0; jt < 2; jt++) {
            int jloc = wc * 16 + jt * 8 + 2 * (l & 3);
            float bx = bias_s[jloc];
            float by = bias_s[jloc + 1];
#pragma unroll
            for (int rr = 0; rr < 2; rr++) {
                int m = blockIdx.y * 128 + wr * 64 + i * 16 + (l >> 2) + rr * 8;
                int t = m >> 6;
                int b = m & 63;
                float2 o = make_float2(acc[i][jt][rr * 2 + 0] + bx,
                                       acc[i][jt][rr * 2 + 1] + by);
                *(float2*)&g_pre[d][t][b][j0 + jloc] = o;
            }
        }
}

// ---------------- persistent HMMA recurrence (R13, unchanged) ------------------
__global__ __launch_bounds__(256, 1) void persist_k(const float* __restrict__ Whf,
                                                    const float* __restrict__ Whb,
                                                    const float* __restrict__ enc_c,
                                                    float* __restrict__ out) {
    extern __shared__ char sm[];
    const uint32_t sb = (uint32_t)__cvta_generic_to_shared(sm);
    __half* Wh_s = (__half*)(sm + SM_WH);
    __half* Wl_s = (__half*)(sm + SM_WL);
    __half (*hb)[8] = (__half(*)[8])(sm + SM_HBUF);           // [64][8]
    const uint32_t mbar = sb + SM_MB;

    const int d   = blockIdx.x >> 6;
    const int n0  = (blockIdx.x & 63) * 8;
    const int tid = threadIdx.x;
    const int w   = tid >> 5;               // warp 0..7
    const int l   = tid & 31;
    const float* __restrict__ W = d ? Whb : Whf;

    unsigned* cnt = &g_cnt[d * 32];

    // ---- convert resident W tile to split fp16 in smem (rows c = nl*4+gate) --
    for (int i = tid; i < 32 * 512; i += 256) {
        int r = i >> 9;
        int k = i & 511;
        int j = (r & 3) * 512 + n0 + (r >> 2);
        float wv = W[(size_t)j * 512 + k];
        __half hi = __float2half_rn(wv);
        __half lo = __float2half_rn(wv - __half2float(hi));
        Wh_s[r * HB + k] = hi;
        Wl_s[r * HB + k] = lo;
    }

    // ---- per-lane geometry (verified R8 layout) ----
    const int m0 = (w & 3) * 16;             // batch stripe
    const int jb = (w >> 2) * 16;            // col base (2 n8 tiles)
    const uint32_t aoff = (uint32_t)(((m0 + (l & 15)) * HB + ((l >> 4) * 8)) * 2);
    const uint32_t boff = (uint32_t)(((jb + ((l >> 4) & 1) * 8 + (l & 7)) * HB
                                      + (((l >> 3) & 1) * 8)) * 2);
    const uint32_t aHb = sb + SM_H + aoff;
    const uint32_t bHb = sb + SM_WH + boff;
    const uint32_t bLb = sb + SM_WL + boff;

    const int b_out = m0 + (l >> 2) + ((l & 1) ? 8 : 0);
    const int nlb   = (jb >> 2) + ((l & 2) >> 1);

    float c_reg[2];
#pragma unroll
    for (int t2 = 0; t2 < 2; t2++)
        c_reg[t2] = enc_c[b_out * 1024 + d * 512 + n0 + nlb + 2 * t2];

    if (tid == 0) mbar_init(mbar, 1);
    __syncthreads();

    if (tid == 0) {
        mbar_expect_tx(mbar, HSLICE);
        bulk_cp(sb + SM_H, &g_hf[0][d][0][0], HSLICE, mbar);
    }
    float pre_cur[2][4], pre_next[2][4];
#pragma unroll
    for (int t2 = 0; t2 < 2; t2++)
#pragma unroll
        for (int g = 0; g < 4; g++)
            pre_cur[t2][g] = __ldcs(&g_pre[d][0][b_out][g * 512 + n0 + nlb + 2 * t2]);

    int mph = 0;
    for (int t = 0; t < 512; t++) {
        const int ph = t & 1;

        if (t + 1 < 512) {
#pragma unroll
            for (int t2 = 0; t2 < 2; t2++)
#pragma unroll
                for (int g = 0; g < 4; g++)
                    pre_next[t2][g] =
                        __ldcs(&g_pre[d][t + 1][b_out][g * 512 + n0 + nlb + 2 * t2]);
        }

        mbar_wait(mbar, mph);
        mph ^= 1;

        float a_h0[4] = {0, 0, 0, 0}, a_h1[4] = {0, 0, 0, 0};
        float a_l0[4] = {0, 0, 0, 0}, a_l1[4] = {0, 0, 0, 0};
#pragma unroll 4
        for (int kk = 0; kk < 512; kk += 16) {
            uint32_t ah[4], bh[4], bl[4];
            ldsm4(ah, aHb + kk * 2);
            ldsm4(bh, bHb + kk * 2);
            ldsm4(bl, bLb + kk * 2);
            mma16816h(a_h0, ah, bh[0], bh[1]);
            mma16816h(a_h1, ah, bh[2], bh[3]);
            mma16816h(a_l0, ah, bl[0], bl[1]);
            mma16816h(a_l1, ah, bl[2], bl[3]);
        }
        float acc0[4], acc1[4];
#pragma unroll
        for (int i = 0; i < 4; i++) {
            acc0[i] = a_h0[i] + a_l0[i];
            acc1[i] = a_h1[i] + a_l1[i];
        }

        const int odd = l & 1;
        float h_res[2];
        float* accs[2] = {acc0, acc1};
#pragma unroll
        for (int t2 = 0; t2 < 2; t2++) {
            float* a = accs[t2];
            float r0 = __shfl_xor_sync(0xFFFFFFFFu, odd ? a[0] : a[2], 1);
            float r1 = __shfl_xor_sync(0xFFFFFFFFu, odd ? a[1] : a[3], 1);
            float g0 = odd ? r0 : a[0];
            float g1 = odd ? r1 : a[1];
            float g2 = odd ? a[2] : r0;
            float g3 = odd ? a[3] : r1;

            float gi = pre_cur[t2][0] + g0;
            float gf = pre_cur[t2][1] + g1;
            float gg = pre_cur[t2][2] + g2;
            float go = pre_cur[t2][3] + g3;
            float si = sigmoid_fast(gi);
            float sf = sigmoid_fast(gf);
            float tg = tanh_fast(gg);
            float so = sigmoid_fast(go);
            float c  = sf * c_reg[t2] + si * tg;
            float h  = so * tanh_fast(c);
            c_reg[t2] = c;
            h_res[t2] = h;

            hb[b_out][nlb + 2 * t2] = __float2half_rn(h);
        }
        __syncthreads();

        if (tid < 64)
            *(uint4*)&g_hf[ph ^ 1][d][tid][n0] = *(const uint4*)&hb[tid][0];

        if (t < 511) {
            __syncthreads();
            if (tid == 0) {
                atom_add_rel(cnt, 1u);
                unsigned target = 64u * (unsigned)(t + 1);
                while (ld_acq(cnt) < target) {}
                mbar_expect_tx(mbar, HSLICE);
                bulk_cp(sb + SM_H, &g_hf[(ph ^ 1)][d][0][0], HSLICE, mbar);
            }
            __syncthreads();
        }

        const int tout = d ? (511 - t) : t;
#pragma unroll
        for (int t2 = 0; t2 < 2; t2++) {
            const int n = n0 + nlb + 2 * t2;
            __stcs(&out[((size_t)b_out * 512 + tout) * 1024 + d * 512 + n], h_res[t2]);
            if (t == 511) {
                __stcs(&out[33554432 + b_out * 1024 + d * 512 + n], h_res[t2]);
                __stcs(&out[33554432 + 65536 + b_out * 1024 + d * 512 + n], c_reg[t2]);
            }
        }

#pragma unroll
        for (int t2 = 0; t2 < 2; t2++)
#pragma unroll
            for (int g = 0; g < 4; g++) pre_cur[t2][g] = pre_next[t2][g];
    }
}

// ---------------- launch -----------------------------------------------------
extern "C" void kernel_launch(void* const* d_in, const int* in_sizes, int n_in,
                              void* d_out, int out_size) {
    const float* x     = (const float*)d_in[0];
    const float* enc_h = (const float*)d_in[1];
    const float* enc_c = (const float*)d_in[2];
    const float* Wih_f = (const float*)d_in[3];
    const float* Whh_f = (const float*)d_in[4];
    const float* b_f   = (const float*)d_in[5];
    const float* Wih_b = (const float*)d_in[6];
    const float* Whh_b = (const float*)d_in[7];
    const float* b_b   = (const float*)d_in[8];
    float* out = (float*)d_out;

    cudaFuncSetAttribute(persist_k, cudaFuncAttributeMaxDynamicSharedMemorySize,
                         PERSIST_SMEM);
    cudaFuncSetAttribute(pre_tc, cudaFuncAttributeMaxDynamicSharedMemorySize,
                         PT_SMEM);

    dummy_k<<<1, 32>>>();
    init_k<<<256, 256>>>(enc_h);
    cvtX_k<<<16384, 256>>>(x);
    cvtW_k<<<2048, 256>>>(Wih_f, Wih_b);
    pre_tc<<<dim3(32, 256, 2), 256, PT_SMEM>>>(b_f, b_b);
    persist_k<<<NCTA, 256, PERSIST_SMEM>>>(Whh_f, Whh_b, enc_c, out);
}